// round 4
// baseline (speedup 1.0000x reference)
#include <cuda_runtime.h>
#include <math.h>

#define BB 64
#define CC 768
#define HH 64
#define WW 64
#define PLANE (HH*WW)           // 4096

// Hermitian-symmetrized full-plane gate, scale folded: [c][kw(0..63)][kh(0..63)]
// 768*64*64 complex = 25.2 MB static device mem
__device__ float2 g_geff[CC * 64 * 64];

// ---------------------------------------------------------------------------
// packed complex: one 64-bit register pair, lo = re, hi = im
// ---------------------------------------------------------------------------
typedef unsigned long long c64;

__device__ __forceinline__ c64 pk(float x, float y){
    c64 r; asm("mov.b64 %0, {%1, %2};" : "=l"(r) : "f"(x), "f"(y)); return r;
}
__device__ __forceinline__ float2 up2(c64 a){
    float2 f; asm("mov.b64 {%0, %1}, %2;" : "=f"(f.x), "=f"(f.y) : "l"(a)); return f;
}
__device__ __forceinline__ c64 pswap(c64 a){       // (re,im) -> (im,re)
    float2 f = up2(a); return pk(f.y, f.x);
}
__device__ __forceinline__ c64 padd(c64 a, c64 b){
    c64 r; asm("add.rn.f32x2 %0, %1, %2;" : "=l"(r) : "l"(a), "l"(b)); return r;
}
__device__ __forceinline__ c64 pmul(c64 a, c64 b){
    c64 r; asm("mul.rn.f32x2 %0, %1, %2;" : "=l"(r) : "l"(a), "l"(b)); return r;
}
__device__ __forceinline__ c64 pfma(c64 a, c64 b, c64 c){   // a*b + c (lanewise)
    c64 r; asm("fma.rn.f32x2 %0, %1, %2, %3;" : "=l"(r) : "l"(a), "l"(b), "l"(c)); return r;
}
// complex multiply by scalar twiddle (wr, wi)
__device__ __forceinline__ c64 pcmul_sc(c64 a, float wr, float wi){
    float2 f = up2(a);
    return pk(fmaf(f.x, wr, -(f.y * wi)), fmaf(f.y, wr, f.x * wi));
}

// ---------------------------------------------------------------------------
// packed 8-point complex FFT, natural order in/out. DIR=-1 fwd, +1 inv.
// All +-i rotations folded into fma.f32x2 with (-+D,+-D) constant pairs.
// ---------------------------------------------------------------------------
template<int DIR>
__device__ __forceinline__ void fft8p(c64 v[8]){
    const float rs = 0.70710678118654752440f;
    const float D  = (DIR < 0) ? -1.0f : 1.0f;
    const c64 N1  = pk(-1.0f, -1.0f);
    const c64 SP  = pk(rs, rs);
    const c64 NSP = pk(-rs, -rs);
    const c64 PD  = pk(-D, D);      // fma(swap(t), PD, c)  == c + i*D*t
    const c64 PD2 = pk(D, -D);      // fma(swap(t), PD2, c) == c - i*D*t

    // stage 1 (stride 4) + W8 twiddles
    c64 b0 = padd(v[0], v[4]);
    c64 b1 = padd(v[1], v[5]);
    c64 b2 = padd(v[2], v[6]);
    c64 b3 = padd(v[3], v[7]);
    c64 b4 = pfma(v[4], N1, v[0]);
    c64 t5 = pfma(v[5], N1, v[1]);
    c64 t6 = pfma(v[6], N1, v[2]);
    c64 t7 = pfma(v[7], N1, v[3]);
    c64 b5 = pmul(pfma(pswap(t5), PD,  t5), SP);    // * ( s, D*s)
    c64 sw6 = pswap(t6);                            // b6 = i*D*t6 (deferred)
    c64 b7 = pmul(pfma(pswap(t7), PD2, t7), NSP);   // * (-s, D*s)
    // stage 2+3 upper half
    c64 c0 = padd(b0, b2);
    c64 c2 = pfma(b2, N1, b0);
    c64 c1 = padd(b1, b3);
    c64 t3 = pfma(b3, N1, b1);
    c64 sw3 = pswap(t3);
    c64 d0 = padd(c0, c1);
    c64 d1 = pfma(c1, N1, c0);
    c64 d2 = pfma(sw3, PD,  c2);
    c64 d3 = pfma(sw3, PD2, c2);
    // stage 2+3 lower half
    c64 c4 = pfma(sw6, PD,  b4);
    c64 c6 = pfma(sw6, PD2, b4);
    c64 c5 = padd(b5, b7);
    c64 u7 = pfma(b7, N1, b5);
    c64 sw7 = pswap(u7);
    c64 d4 = padd(c4, c5);
    c64 d5 = pfma(c5, N1, c4);
    c64 d6 = pfma(sw7, PD,  c6);
    c64 d7 = pfma(sw7, PD2, c6);
    // undo DIF bit-reversal
    v[0]=d0; v[1]=d4; v[2]=d2; v[3]=d6; v[4]=d1; v[5]=d5; v[6]=d3; v[7]=d7;
}

// ---------------------------------------------------------------------------
// 8x8 transpose across 8 lanes, packed values (64-bit shfl = 2x SHFL.32)
// ---------------------------------------------------------------------------
__device__ __forceinline__ void transpose8p(c64 v[8], unsigned mask, int lane8){
    #pragma unroll
    for (int m = 4; m >= 1; m >>= 1){
        bool up = (lane8 & m) != 0;
        #pragma unroll
        for (int i = 0; i < 8; i++){
            if ((i & m) == 0){
                int lo = i, hi = i | m;
                c64 t = up ? v[lo] : v[hi];
                t = __shfl_xor_sync(mask, t, m);
                if (up) v[lo] = t; else v[hi] = t;
            }
        }
    }
}

// ---------------------------------------------------------------------------
// 64-pt FFT over 8 lanes (radix 8x8 four-step).
// Layout invariant (in AND out): element index = 8*reg + lane8. Chains freely.
// wr/wi: per-lane forward twiddles e^{-2pi i * j*m/64}
// ---------------------------------------------------------------------------
template<int DIR>
__device__ __forceinline__ void fft64p(c64 v[8], const float wr[8], const float wi[8],
                                       unsigned mask, int j){
    fft8p<DIR>(v);
    #pragma unroll
    for (int m = 1; m < 8; m++)
        v[m] = pcmul_sc(v[m], wr[m], (DIR < 0) ? wi[m] : -wi[m]);
    transpose8p(v, mask, j);
    fft8p<DIR>(v);
}

// ---------------------------------------------------------------------------
// prep: build Hermitian-symmetrized full-plane gate (scale 1/4096 folded)
//   kw<=32          : G[kh][kw]    (symmetrized over kh at kw=0,32)
//   kw> 32          : conj(G[(64-kh)%64][64-kw])
// thread = c*4096 + kw*64 + kh  -> coalesced writes; scattered reads hit L2
// ---------------------------------------------------------------------------
__global__ void prep_geff_kernel(const float* __restrict__ w){
    int idx = blockIdx.x * blockDim.x + threadIdx.x;
    if (idx >= CC * 64 * 64) return;
    int c   = idx >> 12;
    int rem = idx & 4095;
    int kw  = rem >> 6;
    int kh  = rem & 63;
    const float2* W = (const float2*)w;   // float2 index = (kh*33 + k)*CC + c
    float2 g;
    if (kw <= 32){
        g = W[(kh * 33 + kw) * CC + c];
        if (kw == 0 || kw == 32){
            float2 m = W[(((64 - kh) & 63) * 33 + kw) * CC + c];
            g.x = 0.5f * (g.x + m.x);
            g.y = 0.5f * (g.y - m.y);
        }
    } else {
        float2 m = W[(((64 - kh) & 63) * 33 + (64 - kw)) * CC + c];
        g.x =  m.x;
        g.y = -m.y;
    }
    const float S = 1.0f / 4096.0f;       // ortho fwd * ortho inv
    g.x *= S; g.y *= S;
    g_geff[idx] = g;
}

// ---------------------------------------------------------------------------
// main: one CTA per plane-PAIR (b, b+1 at same channel c). z = x0 + i*x1.
// Full complex 2D FFT -> Hermitian gate -> inverse; Re -> plane0, Im -> plane1.
// 256 threads = 32 groups of 8 lanes; each group: 2 rows, 2 cols, 2 rows.
// ---------------------------------------------------------------------------
__global__ __launch_bounds__(256)
void sgn2_kernel(const float* __restrict__ x, float* __restrict__ out){
    __shared__ __align__(16) c64 Sg[64 * 66];   // [kw][r], stride 66

    const int t    = threadIdx.x;
    const int j    = t & 7;
    const int g    = t >> 3;
    const int lane = t & 31;
    const unsigned mask = 0xFFu << (lane & 24);

    const int pc = blockIdx.x;            // bp*CC + c
    const int c  = pc % CC;
    const int bp = pc / CC;
    const float* xp0 = x + ((size_t)(2 * bp) * CC + c) * PLANE;
    const float* xp1 = xp0 + (size_t)CC * PLANE;
    float* op0 = out + ((size_t)(2 * bp) * CC + c) * PLANE;
    float* op1 = op0 + (size_t)CC * PLANE;

    // per-lane forward twiddles e^{-2pi i j*m/64}
    float wr[8], wi[8];
    #pragma unroll
    for (int m = 0; m < 8; m++){
        float sv, cv;
        sincospif((float)(j * m) * (1.0f / 32.0f), &sv, &cv);
        wr[m] = cv; wi[m] = -sv;
    }

    // ---------------- forward rows (W axis): rows g and g+32 ----------------
    #pragma unroll 1
    for (int it = 0; it < 2; it++){
        const int r = g + 32 * it;
        c64 v[8];
        #pragma unroll
        for (int n1 = 0; n1 < 8; n1++){
            int wdx = r * 64 + 8 * n1 + j;
            v[n1] = pk(xp0[wdx], xp1[wdx]);
        }
        fft64p<-1>(v, wr, wi, mask, j);
        #pragma unroll
        for (int k2 = 0; k2 < 8; k2++) Sg[(j + 8 * k2) * 66 + r] = v[k2];
    }
    __syncthreads();

    // ---- columns (H axis): fwd FFT -> gate -> inv FFT, chained in regs -----
    const float2* __restrict__ gbase = g_geff + (size_t)c * 4096;
    #pragma unroll 1
    for (int it = 0; it < 2; it++){
        const int q = g + 32 * it;        // kw column
        c64 u[8];
        #pragma unroll
        for (int n1 = 0; n1 < 8; n1++) u[n1] = Sg[q * 66 + 8 * n1 + j];
        fft64p<-1>(u, wr, wi, mask, j);
        const float2* gq = gbase + q * 64;
        #pragma unroll
        for (int k2 = 0; k2 < 8; k2++){
            float2 wv = gq[j + 8 * k2];
            u[k2] = pcmul_sc(u[k2], wv.x, wv.y);
        }
        fft64p<1>(u, wr, wi, mask, j);
        #pragma unroll
        for (int n2 = 0; n2 < 8; n2++) Sg[q * 66 + j + 8 * n2] = u[n2];
    }
    __syncthreads();

    // ---------------- inverse rows (W axis): Re->p0, Im->p1 -----------------
    #pragma unroll 1
    for (int it = 0; it < 2; it++){
        const int r = g + 32 * it;
        c64 v[8];
        #pragma unroll
        for (int n1 = 0; n1 < 8; n1++) v[n1] = Sg[(8 * n1 + j) * 66 + r];
        fft64p<1>(v, wr, wi, mask, j);
        #pragma unroll
        for (int k2 = 0; k2 < 8; k2++){
            float2 f = up2(v[k2]);
            int wdx = r * 64 + j + 8 * k2;
            op0[wdx] = f.x;
            op1[wdx] = f.y;
        }
    }
}

// ---------------------------------------------------------------------------
extern "C" void kernel_launch(void* const* d_in, const int* in_sizes, int n_in,
                              void* d_out, int out_size){
    const float* x;
    const float* w;
    if (in_sizes[0] == BB * CC * HH * WW){
        x = (const float*)d_in[0];
        w = (const float*)d_in[1];
    } else {
        x = (const float*)d_in[1];
        w = (const float*)d_in[0];
    }
    prep_geff_kernel<<<(CC * 64 * 64 + 255) / 256, 256>>>(w);
    sgn2_kernel<<<(BB / 2) * CC, 256>>>(x, (float*)d_out);
}

// round 6
// speedup vs baseline: 1.5397x; 1.5397x over previous
#include <cuda_runtime.h>
#include <math.h>

#define BB 64
#define CC 768
#define HH 64
#define WW 64
#define PLANE (HH*WW)           // 4096

// Hermitian-symmetrized full-plane gate, ortho^2 scale folded:
// [c][kw(0..63)][kh(0..63)], 25.2 MB static device mem (proven in Round 3)
__device__ float2 g_geff[CC * 64 * 64];

// ---------------------------------------------------------------------------
// complex helpers (scalar float2 — the proven Round-2 engine)
// ---------------------------------------------------------------------------
__device__ __forceinline__ float2 cadd(float2 a, float2 b){ return make_float2(a.x+b.x, a.y+b.y); }
__device__ __forceinline__ float2 csub(float2 a, float2 b){ return make_float2(a.x-b.x, a.y-b.y); }
__device__ __forceinline__ float2 cmul(float2 a, float2 b){
    return make_float2(fmaf(a.x,b.x,-a.y*b.y), fmaf(a.x,b.y, a.y*b.x));
}
template<int DIR>
__device__ __forceinline__ float2 muli(float2 a){
    return (DIR < 0) ? make_float2(a.y, -a.x) : make_float2(-a.y, a.x);
}

// ---------------------------------------------------------------------------
// 8-point complex FFT on registers, natural order in/out. Unnormalized.
// ---------------------------------------------------------------------------
template<int DIR>
__device__ __forceinline__ void fft8(float2 v[8]){
    const float s = 0.70710678118654752440f;
    float2 b0 = cadd(v[0], v[4]);
    float2 b1 = cadd(v[1], v[5]);
    float2 b2 = cadd(v[2], v[6]);
    float2 b3 = cadd(v[3], v[7]);
    float2 b4 = csub(v[0], v[4]);
    float2 b5 = csub(v[1], v[5]);
    float2 b6 = csub(v[2], v[6]);
    float2 b7 = csub(v[3], v[7]);
    b5 = cmul(b5, make_float2( s, DIR * s));
    b6 = muli<DIR>(b6);
    b7 = cmul(b7, make_float2(-s, DIR * s));
    float2 c0 = cadd(b0, b2), c2 = csub(b0, b2);
    float2 c1 = cadd(b1, b3), c3 = csub(b1, b3);
    c3 = muli<DIR>(c3);
    float2 c4 = cadd(b4, b6), c6 = csub(b4, b6);
    float2 c5 = cadd(b5, b7), c7 = csub(b5, b7);
    c7 = muli<DIR>(c7);
    float2 d0 = cadd(c0, c1), d1 = csub(c0, c1);
    float2 d2 = cadd(c2, c3), d3 = csub(c2, c3);
    float2 d4 = cadd(c4, c5), d5 = csub(c4, c5);
    float2 d6 = cadd(c6, c7), d7 = csub(c6, c7);
    v[0]=d0; v[1]=d4; v[2]=d2; v[3]=d6; v[4]=d1; v[5]=d5; v[6]=d3; v[7]=d7;
}

// ---------------------------------------------------------------------------
// 8x8 transpose across the 8 lanes of a group
// ---------------------------------------------------------------------------
__device__ __forceinline__ void transpose8(float2 v[8], unsigned mask, int lane8){
    #pragma unroll
    for (int m = 4; m >= 1; m >>= 1){
        bool up = (lane8 & m) != 0;
        #pragma unroll
        for (int i = 0; i < 8; i++){
            if ((i & m) == 0){
                int lo = i, hi = i | m;
                float2 t = up ? v[lo] : v[hi];
                t.x = __shfl_xor_sync(mask, t.x, m);
                t.y = __shfl_xor_sync(mask, t.y, m);
                if (up) v[lo] = t; else v[hi] = t;
            }
        }
    }
}

// ---------------------------------------------------------------------------
// 64-pt FFT over 8 lanes (radix 8x8 four-step).
// Layout invariant (in AND out): element index = 8*reg + lane. Chains freely.
// twf[m] = e^{-2*pi*i * j*m / 64}
// ---------------------------------------------------------------------------
template<int DIR>
__device__ __forceinline__ void fft64(float2 v[8], const float2 twf[8],
                                      unsigned mask, int j){
    fft8<DIR>(v);
    #pragma unroll
    for (int m = 1; m < 8; m++){
        float2 w = twf[m];
        if (DIR > 0) w.y = -w.y;
        v[m] = cmul(v[m], w);
    }
    transpose8(v, mask, j);
    fft8<DIR>(v);
}

// ---------------------------------------------------------------------------
// prep: Hermitian-symmetrized full-plane gate, 1/4096 folded (Round-3 proven)
// ---------------------------------------------------------------------------
__global__ void prep_geff_kernel(const float* __restrict__ w){
    int idx = blockIdx.x * blockDim.x + threadIdx.x;
    if (idx >= CC * 64 * 64) return;
    int c   = idx >> 12;
    int rem = idx & 4095;
    int kw  = rem >> 6;
    int kh  = rem & 63;
    const float2* W = (const float2*)w;   // float2 index = (kh*33 + k)*CC + c
    float2 g;
    if (kw <= 32){
        g = W[(kh * 33 + kw) * CC + c];
        if (kw == 0 || kw == 32){
            float2 m = W[(((64 - kh) & 63) * 33 + kw) * CC + c];
            g.x = 0.5f * (g.x + m.x);
            g.y = 0.5f * (g.y - m.y);
        }
    } else {
        float2 m = W[(((64 - kh) & 63) * 33 + (64 - kw)) * CC + c];
        g.x =  m.x;
        g.y = -m.y;
    }
    const float S = 1.0f / 4096.0f;
    g.x *= S; g.y *= S;
    g_geff[idx] = g;
}

// ---------------------------------------------------------------------------
// main: one CTA per plane-PAIR (batches 2bp, 2bp+1 at channel c). z = x0 + i*x1.
// Full complex 2D FFT -> Hermitian gate -> inverse; Re -> plane0, Im -> plane1.
// 256 threads = 32 groups of 8 lanes; each group: 2 rows, 2 cols, 2 rows.
// ---------------------------------------------------------------------------
__global__ __launch_bounds__(256)
void sgn3_kernel(const float* __restrict__ x, float* __restrict__ out){
    __shared__ __align__(16) float2 Sg[64 * 66];   // [kw][h], row stride 66

    const int t    = threadIdx.x;
    const int j    = t & 7;
    const int g    = t >> 3;
    const int lane = t & 31;
    const unsigned mask = 0xFFu << (lane & 24);

    const int pc = blockIdx.x;            // bp*CC + c
    const int c  = pc % CC;
    const int bp = pc / CC;
    const float* xp0 = x + ((size_t)(2 * bp) * CC + c) * PLANE;
    const float* xp1 = xp0 + (size_t)CC * PLANE;
    float* op0 = out + ((size_t)(2 * bp) * CC + c) * PLANE;
    float* op1 = op0 + (size_t)CC * PLANE;

    // per-lane forward twiddles e^{-2pi i j*m/64}
    float2 twf[8];
    #pragma unroll
    for (int m = 0; m < 8; m++){
        float sv, cv;
        sincospif((float)(j * m) * (1.0f / 32.0f), &sv, &cv);
        twf[m] = make_float2(cv, -sv);
    }

    // ---------------- forward rows (W axis): rows g and g+32 ----------------
    #pragma unroll 1
    for (int it = 0; it < 2; it++){
        const int r = g + 32 * it;
        float2 v[8];
        #pragma unroll
        for (int n1 = 0; n1 < 8; n1++){
            int wdx = r * 64 + 8 * n1 + j;
            v[n1] = make_float2(xp0[wdx], xp1[wdx]);
        }
        fft64<-1>(v, twf, mask, j);               // v[k2] = Z[r][kw=j+8k2]
        #pragma unroll
        for (int k2 = 0; k2 < 8; k2++) Sg[(j + 8 * k2) * 66 + r] = v[k2];
    }
    __syncthreads();

    // ---- columns (H axis): fwd FFT -> gate -> inv FFT, chained in regs -----
    const float2* __restrict__ gbase = g_geff + (size_t)c * 4096;
    #pragma unroll 1
    for (int it = 0; it < 2; it++){
        const int q = g + 32 * it;        // kw column
        float2 u[8];
        #pragma unroll
        for (int n1 = 0; n1 < 8; n1++) u[n1] = Sg[q * 66 + 8 * n1 + j];
        fft64<-1>(u, twf, mask, j);               // u[k2] = Xf[kh=j+8k2][q]
        const float2* gq = gbase + q * 64;
        #pragma unroll
        for (int k2 = 0; k2 < 8; k2++)
            u[k2] = cmul(u[k2], gq[j + 8 * k2]);
        fft64<1>(u, twf, mask, j);                // u[n2] = y[h=j+8n2][q]
        #pragma unroll
        for (int n2 = 0; n2 < 8; n2++) Sg[q * 66 + j + 8 * n2] = u[n2];
    }
    __syncthreads();

    // ---------------- inverse rows (W axis): Re->p0, Im->p1 -----------------
    #pragma unroll 1
    for (int it = 0; it < 2; it++){
        const int r = g + 32 * it;
        float2 v[8];
        #pragma unroll
        for (int n1 = 0; n1 < 8; n1++) v[n1] = Sg[(8 * n1 + j) * 66 + r];
        fft64<1>(v, twf, mask, j);                // v[k2] = z_out[r][w=j+8k2]
        #pragma unroll
        for (int k2 = 0; k2 < 8; k2++){
            int wdx = r * 64 + j + 8 * k2;
            op0[wdx] = v[k2].x;
            op1[wdx] = v[k2].y;
        }
    }
}

// ---------------------------------------------------------------------------
extern "C" void kernel_launch(void* const* d_in, const int* in_sizes, int n_in,
                              void* d_out, int out_size){
    const float* x;
    const float* w;
    if (in_sizes[0] == BB * CC * HH * WW){
        x = (const float*)d_in[0];
        w = (const float*)d_in[1];
    } else {
        x = (const float*)d_in[1];
        w = (const float*)d_in[0];
    }
    prep_geff_kernel<<<(CC * 64 * 64 + 255) / 256, 256>>>(w);
    sgn3_kernel<<<(BB / 2) * CC, 256>>>(x, (float*)d_out);
}